// round 1
// baseline (speedup 1.0000x reference)
#include <cuda_runtime.h>

// HybridConv: out[n] = F(dot(data[n], conv_w) + conv_b) where F is a fixed
// scalar function (sigmoid -> RBF(8x4 basis) -> MLP 8->16->1 with tanh).
// Strategy: tabulate G(act) once per launch (tiny kernel), then the main
// kernel is a pure streaming pass: 16B load -> dot -> sigmoid -> shared-mem
// table lerp -> 4B store. DRAM-bound at ~168 MB total traffic.

#define T_TAB 8192
#define N_BASIS 8
#define N_HIDDEN 16

// Table of (value, next-value-minus-value) pairs over act in [0,1].
__device__ float2 g_table[T_TAB];

__global__ void build_table_kernel(const float* __restrict__ basis,
                                   const float* __restrict__ w1,
                                   const float* __restrict__ b1,
                                   const float* __restrict__ w2,
                                   const float* __restrict__ b2) {
    int i = blockIdx.x * blockDim.x + threadIdx.x;
    if (i >= T_TAB) return;

    float v[2];
#pragma unroll
    for (int e = 0; e < 2; e++) {
        int ii = i + e;
        if (ii > T_TAB - 1) ii = T_TAB - 1;
        float a = (float)ii * (1.0f / (float)(T_TAB - 1));

        float feat[N_BASIS];
#pragma unroll
        for (int r = 0; r < N_BASIS; r++) {
            float q = 0.0f;
#pragma unroll
            for (int j = 0; j < 4; j++) {
                float d = a - basis[r * 4 + j];
                q = fmaf(d, d, q);
            }
            feat[r] = expf(-q);   // GAMMA = 1
        }

        float out = b2[0];
#pragma unroll
        for (int k = 0; k < N_HIDDEN; k++) {
            float s = b1[k];
#pragma unroll
            for (int r = 0; r < N_BASIS; r++)
                s = fmaf(feat[r], w1[r * N_HIDDEN + k], s);
            out = fmaf(tanhf(s), w2[k], out);
        }
        v[e] = out;
    }
    g_table[i] = make_float2(v[0], v[1] - v[0]);
}

__device__ __forceinline__ float eval_patch(float4 d, float w0, float w1f,
                                            float w2f, float w3, float cb,
                                            const float2* s_tab) {
    float logit = fmaf(d.x, w0, fmaf(d.y, w1f, fmaf(d.z, w2f, fmaf(d.w, w3, cb))));
    // sigmoid (fast path): 1 / (1 + e^-x); saturates cleanly at extremes.
    float e = __expf(-logit);
    float act = __saturatef(__fdividef(1.0f, 1.0f + e));
    float p = act * (float)(T_TAB - 1);
    int idx = (int)p;
    float frac = p - (float)idx;
    float2 t = s_tab[idx];
    return fmaf(frac, t.y, t.x);
}

__global__ void __launch_bounds__(256, 3)
hybrid_main_kernel(const float4* __restrict__ data4,
                   const float* __restrict__ conv_w,
                   const float* __restrict__ conv_b,
                   float4* __restrict__ out4, int items /* = N/4 */) {
    extern __shared__ float2 s_tab[];
    // Cooperative copy of the 64 KB table into shared memory.
    for (int i = threadIdx.x; i < T_TAB; i += blockDim.x)
        s_tab[i] = g_table[i];
    __syncthreads();

    const float w0 = __ldg(conv_w + 0);
    const float w1f = __ldg(conv_w + 1);
    const float w2f = __ldg(conv_w + 2);
    const float w3 = __ldg(conv_w + 3);
    const float cb = __ldg(conv_b);

    const int stride = gridDim.x * blockDim.x;
    for (int idx = blockIdx.x * blockDim.x + threadIdx.x; idx < items; idx += stride) {
        // 4 consecutive patches per thread -> one float4 store.
        const float4* p = data4 + 4 * idx;
        float4 d0 = p[0];
        float4 d1 = p[1];
        float4 d2 = p[2];
        float4 d3 = p[3];

        float4 o;
        o.x = eval_patch(d0, w0, w1f, w2f, w3, cb, s_tab);
        o.y = eval_patch(d1, w0, w1f, w2f, w3, cb, s_tab);
        o.z = eval_patch(d2, w0, w1f, w2f, w3, cb, s_tab);
        o.w = eval_patch(d3, w0, w1f, w2f, w3, cb, s_tab);
        out4[idx] = o;
    }
}

extern "C" void kernel_launch(void* const* d_in, const int* in_sizes, int n_in,
                              void* d_out, int out_size) {
    const float* data   = (const float*)d_in[0];
    const float* conv_w = (const float*)d_in[1];
    const float* conv_b = (const float*)d_in[2];
    const float* basis  = (const float*)d_in[3];
    const float* w1     = (const float*)d_in[4];
    const float* b1     = (const float*)d_in[5];
    const float* w2     = (const float*)d_in[6];
    const float* b2     = (const float*)d_in[7];

    const int N = in_sizes[0] / 4;       // patches
    const int items = N / 4;             // float4 outputs (N % 4 == 0 here)

    build_table_kernel<<<(T_TAB + 255) / 256, 256>>>(basis, w1, b1, w2, b2);

    static_assert(sizeof(float2) * T_TAB == 65536, "table smem size");
    cudaFuncSetAttribute(hybrid_main_kernel,
                         cudaFuncAttributeMaxDynamicSharedMemorySize, 65536);

    // Persistent-style grid: 3 CTAs/SM * 148 SMs; grid-stride covers all items.
    hybrid_main_kernel<<<444, 256, 65536>>>(
        (const float4*)data, conv_w, conv_b, (float4*)d_out, items);
}

// round 4
// speedup vs baseline: 1.0548x; 1.0548x over previous
#include <cuda_runtime.h>

// HybridConv: out[n] = F(dot(data[n], conv_w) + conv_b) where F is a fixed
// scalar function (sigmoid -> RBF(8x4 basis) -> MLP 8->16->1 with tanh).
// Tabulate G(act) on a 2048-point grid (16 KB float2 table -> 8 CTAs/SM),
// then stream: 16B load -> dot -> sigmoid -> shared lerp -> 4B store.

#define T_TAB 2048
#define N_BASIS 8
#define N_HIDDEN 16

// Table of (value, next-value-minus-value) pairs over act in [0,1].
__device__ float2 g_table[T_TAB];

__global__ void build_table_kernel(const float* __restrict__ basis,
                                   const float* __restrict__ w1,
                                   const float* __restrict__ b1,
                                   const float* __restrict__ w2,
                                   const float* __restrict__ b2) {
    int i = blockIdx.x * blockDim.x + threadIdx.x;
    if (i >= T_TAB) return;

    float v[2];
#pragma unroll
    for (int e = 0; e < 2; e++) {
        int ii = i + e;
        if (ii > T_TAB - 1) ii = T_TAB - 1;
        float a = (float)ii * (1.0f / (float)(T_TAB - 1));

        float feat[N_BASIS];
#pragma unroll
        for (int r = 0; r < N_BASIS; r++) {
            float q = 0.0f;
#pragma unroll
            for (int j = 0; j < 4; j++) {
                float d = a - basis[r * 4 + j];
                q = fmaf(d, d, q);
            }
            feat[r] = expf(-q);   // GAMMA = 1
        }

        float out = b2[0];
#pragma unroll
        for (int k = 0; k < N_HIDDEN; k++) {
            float s = b1[k];
#pragma unroll
            for (int r = 0; r < N_BASIS; r++)
                s = fmaf(feat[r], w1[r * N_HIDDEN + k], s);
            out = fmaf(tanhf(s), w2[k], out);
        }
        v[e] = out;
    }
    g_table[i] = make_float2(v[0], v[1] - v[0]);
}

__device__ __forceinline__ float eval_patch(float4 d, float w0, float w1f,
                                            float w2f, float w3, float cb,
                                            const float2* s_tab) {
    float logit = fmaf(d.x, w0, fmaf(d.y, w1f, fmaf(d.z, w2f, fmaf(d.w, w3, cb))));
    // sigmoid (fast path): 1 / (1 + e^-x); saturates cleanly at extremes.
    float e = __expf(-logit);
    float act = __saturatef(__fdividef(1.0f, 1.0f + e));
    float p = act * (float)(T_TAB - 1);
    int idx = (int)p;
    float frac = p - (float)idx;
    float2 t = s_tab[idx];
    return fmaf(frac, t.y, t.x);
}

__global__ void __launch_bounds__(256, 8)
hybrid_main_kernel(const float4* __restrict__ data4,
                   const float* __restrict__ conv_w,
                   const float* __restrict__ conv_b,
                   float4* __restrict__ out4, int items /* = N/4 */) {
    __shared__ float2 s_tab[T_TAB];
    // Cooperative copy of the 16 KB table into shared memory (hits L2 after
    // the first CTA touches it).
    for (int i = threadIdx.x; i < T_TAB; i += blockDim.x)
        s_tab[i] = g_table[i];
    __syncthreads();

    const float w0 = __ldg(conv_w + 0);
    const float w1f = __ldg(conv_w + 1);
    const float w2f = __ldg(conv_w + 2);
    const float w3 = __ldg(conv_w + 3);
    const float cb = __ldg(conv_b);

    const int stride = gridDim.x * blockDim.x;
    for (int idx = blockIdx.x * blockDim.x + threadIdx.x; idx < items; idx += stride) {
        // 4 consecutive patches per thread -> one float4 store.
        const float4* p = data4 + 4 * idx;
        float4 d0 = p[0];
        float4 d1 = p[1];
        float4 d2 = p[2];
        float4 d3 = p[3];

        float4 o;
        o.x = eval_patch(d0, w0, w1f, w2f, w3, cb, s_tab);
        o.y = eval_patch(d1, w0, w1f, w2f, w3, cb, s_tab);
        o.z = eval_patch(d2, w0, w1f, w2f, w3, cb, s_tab);
        o.w = eval_patch(d3, w0, w1f, w2f, w3, cb, s_tab);
        out4[idx] = o;
    }
}

extern "C" void kernel_launch(void* const* d_in, const int* in_sizes, int n_in,
                              void* d_out, int out_size) {
    const float* data   = (const float*)d_in[0];
    const float* conv_w = (const float*)d_in[1];
    const float* conv_b = (const float*)d_in[2];
    const float* basis  = (const float*)d_in[3];
    const float* w1     = (const float*)d_in[4];
    const float* b1     = (const float*)d_in[5];
    const float* w2     = (const float*)d_in[6];
    const float* b2     = (const float*)d_in[7];

    const int N = in_sizes[0] / 4;       // patches
    const int items = N / 4;             // float4 outputs (N % 4 == 0 here)

    build_table_kernel<<<(T_TAB + 255) / 256, 256>>>(basis, w1, b1, w2, b2);

    // Persistent grid: 8 CTAs/SM * 148 SMs = 1184; grid-stride covers all items.
    hybrid_main_kernel<<<1184, 256>>>(
        (const float4*)data, conv_w, conv_b, (float4*)d_out, items);
}